// round 2
// baseline (speedup 1.0000x reference)
#include <cuda_runtime.h>
#include <cstdint>
#include <math.h>

// ---------------- problem constants ----------------
#define NTOK   4096      // B*T
#define TSEQ   512
#define NBATCH 8
#define DIMIN  768
#define WIDTH  8192
#define NHEADS 8
#define NEMBDS 128
#define DHQK   16
#define DHV    1024
#define KVAL   32
#define LAM    (1.0f/3072.0f)   // 1/(4*DIMIN)

// ---------------- scratch (device globals; no allocation allowed) ----------------
__device__ float g_x   [NTOK*DIMIN];
__device__ float g_x2  [NTOK*DIMIN];
__device__ float g_zin [(size_t)NTOK*WIDTH];   // reused for z_novel
__device__ float g_zctx[(size_t)NTOK*WIDTH];
__device__ float g_q   [NTOK*NEMBDS];
__device__ float g_k   [NTOK*NEMBDS];
__device__ float g_v   [(size_t)NTOK*WIDTH];
__device__ float g_att [(size_t)NBATCH*NHEADS*TSEQ*TSEQ];
__device__ float g_o   [(size_t)NTOK*WIDTH];
__device__ float g_zp  [(size_t)NTOK*WIDTH];
__device__ float g_Dz  [NTOK*DIMIN];
__device__ float g_proj[NTOK];
__device__ float g_tkv [NTOK*KVAL];
__device__ int   g_tki [NTOK*KVAL];

// ---------------- generic tiled SGEMM ----------------
// BMODE 0: B is (N x K) row-major weight  -> C = A * B^T
// BMODE 1: B is (K x N) row-major         -> C = A * B
// 128x128 block tile, BK=8, 256 threads, 8x8 per-thread microtile.
#define BM 128
#define BN 128
#define BK 8

template<int BMODE, bool RELU, bool HAS_BIAS>
__global__ void __launch_bounds__(256) sgemm_kernel(
    const float* __restrict__ Ag, const float* __restrict__ Bg,
    float* __restrict__ Cg, const float* __restrict__ bias,
    int K, int lda, int ldb, int ldc, float alpha,
    long sA, long sB1, long sB2, long sC1, long sC2, int zdiv)
{
    if (gridDim.z > 1) {
        int z = blockIdx.z;
        int zb = z / zdiv, zh = z % zdiv;
        Ag += (long)z * sA;
        Bg += (long)zb * sB1 + (long)zh * sB2;
        Cg += (long)zb * sC1 + (long)zh * sC2;
    }
    __shared__ float As[BK][BM];
    __shared__ float Bs[BK][BN];

    const int tid = threadIdx.x;
    const int bm = blockIdx.y * BM;
    const int bn = blockIdx.x * BN;
    const int tr = tid >> 4;       // 0..15
    const int tc = tid & 15;       // 0..15
    const int lr = tid >> 1;       // 0..127 (row within tile for A / weight-B)
    const int lc = (tid & 1) * 4;  // 0 or 4 (k offset)
    const int nr = tid >> 5;       // 0..7  (k row for NN-B)
    const int nc = (tid & 31) * 4; // 0..124

    float acc[8][8];
    #pragma unroll
    for (int i = 0; i < 8; i++)
        #pragma unroll
        for (int j = 0; j < 8; j++) acc[i][j] = 0.f;

    const float* Aptr  = Ag + (long)(bm + lr) * lda + lc;
    const float* BptrW = Bg + (long)(bn + lr) * ldb + lc;
    const float* BptrN = Bg + (long)nr * ldb + bn + nc;

    for (int k0 = 0; k0 < K; k0 += BK) {
        float4 a4 = *(const float4*)(Aptr + k0);
        As[lc+0][lr] = a4.x; As[lc+1][lr] = a4.y;
        As[lc+2][lr] = a4.z; As[lc+3][lr] = a4.w;
        if (BMODE == 0) {
            float4 b4 = *(const float4*)(BptrW + k0);
            Bs[lc+0][lr] = b4.x; Bs[lc+1][lr] = b4.y;
            Bs[lc+2][lr] = b4.z; Bs[lc+3][lr] = b4.w;
        } else {
            float4 b4 = *(const float4*)(BptrN + (long)k0 * ldb);
            *(float4*)&Bs[nr][nc] = b4;
        }
        __syncthreads();
        #pragma unroll
        for (int kk = 0; kk < BK; kk++) {
            float ra[8], rb[8];
            *(float4*)(ra)   = *(const float4*)&As[kk][tr*8];
            *(float4*)(ra+4) = *(const float4*)&As[kk][tr*8+4];
            *(float4*)(rb)   = *(const float4*)&Bs[kk][tc*8];
            *(float4*)(rb+4) = *(const float4*)&Bs[kk][tc*8+4];
            #pragma unroll
            for (int i = 0; i < 8; i++)
                #pragma unroll
                for (int j = 0; j < 8; j++)
                    acc[i][j] += ra[i] * rb[j];
        }
        __syncthreads();
    }

    #pragma unroll
    for (int i = 0; i < 8; i++) {
        const int m = bm + tr*8 + i;
        float* crow = Cg + (long)m * ldc + bn + tc*8;
        #pragma unroll
        for (int jj = 0; jj < 8; jj += 4) {
            float4 o4;
            float vv[4];
            #pragma unroll
            for (int t = 0; t < 4; t++) {
                float v = alpha * acc[i][jj+t];
                if (HAS_BIAS) v += bias[bn + tc*8 + jj + t];
                if (RELU) v = fmaxf(v, 0.f);
                vv[t] = v;
            }
            o4.x = vv[0]; o4.y = vv[1]; o4.z = vv[2]; o4.w = vv[3];
            *(float4*)(crow + jj) = o4;
        }
    }
}

// ---------------- elementwise / glue kernels ----------------
__global__ void sub_b_kernel(const float* __restrict__ xin, const float* __restrict__ b)
{
    int i = blockIdx.x * 256 + threadIdx.x;   // exactly NTOK*DIMIN threads
    g_x[i] = xin[i] - b[i % DIMIN];
}

__global__ void shift_kernel()
{
    long i = (long)blockIdx.x * 256 + threadIdx.x;  // NTOK*WIDTH threads
    long tok = i >> 13;              // / WIDTH
    int  t   = (int)(tok & (TSEQ-1));
    g_zctx[i] = (t == 0) ? 0.f : g_zin[i - WIDTH];
}

// scores + causal softmax; one block per (bh, t)
__global__ void attn_softmax_kernel()
{
    const int t  = blockIdx.x;
    const int bh = blockIdx.y;
    const int b  = bh >> 3, h = bh & 7;
    __shared__ float qs[DHQK];
    __shared__ float sc[TSEQ];
    __shared__ float red[128];
    const int tid = threadIdx.x;  // 128

    if (tid < DHQK) qs[tid] = g_q[(long)(b*TSEQ + t)*NEMBDS + h*DHQK + tid];
    __syncthreads();

    float lmax = -1e30f;
    for (int s = tid; s < TSEQ; s += 128) {
        float val = -1e30f;
        if (s <= t) {
            const float* kp = g_k + (long)(b*TSEQ + s)*NEMBDS + h*DHQK;
            float d = 0.f;
            #pragma unroll
            for (int i = 0; i < DHQK; i++) d += qs[i] * kp[i];
            val = d * 0.25f;   // / sqrt(16)
        }
        sc[s] = val;
        lmax = fmaxf(lmax, val);
    }
    red[tid] = lmax; __syncthreads();
    for (int o = 64; o > 0; o >>= 1) { if (tid < o) red[tid] = fmaxf(red[tid], red[tid+o]); __syncthreads(); }
    const float mx = red[0];
    __syncthreads();

    float lsum = 0.f;
    for (int s = tid; s < TSEQ; s += 128) {
        float e = (s <= t) ? expf(sc[s] - mx) : 0.f;
        sc[s] = e; lsum += e;
    }
    red[tid] = lsum; __syncthreads();
    for (int o = 64; o > 0; o >>= 1) { if (tid < o) red[tid] += red[tid+o]; __syncthreads(); }
    const float inv = 1.f / red[0];

    float* ap = g_att + ((long)bh * TSEQ + t) * TSEQ;
    for (int s = tid; s < TSEQ; s += 128) ap[s] = sc[s] * inv;
}

// proj + residual update; one block per token
__global__ void proj_kernel()
{
    const int tok = blockIdx.x, tid = threadIdx.x;  // 256
    const float* dz = g_Dz + (long)tok * DIMIN;
    const float* xx = g_x  + (long)tok * DIMIN;
    float d1 = 0.f, d2 = 0.f;
    for (int i = tid; i < DIMIN; i += 256) { float a = dz[i]; d1 += a * xx[i]; d2 += a * a; }
    __shared__ float r1[256], r2[256];
    r1[tid] = d1; r2[tid] = d2; __syncthreads();
    for (int o = 128; o > 0; o >>= 1) { if (tid < o) { r1[tid] += r1[tid+o]; r2[tid] += r2[tid+o]; } __syncthreads(); }
    const float p = r1[0] / (r2[0] + 1e-6f);
    if (tid == 0) g_proj[tok] = p;
    for (int i = tid; i < DIMIN; i += 256)
        g_x2[(long)tok*DIMIN + i] = xx[i] - p * dz[i];
}

// top-32 of z_novel row (stored in g_zin); one block per token
__global__ void topk_kernel()
{
    const int tok = blockIdx.x, tid = threadIdx.x;  // 256
    __shared__ float vals[WIDTH];
    __shared__ unsigned char sel[WIDTH];
    __shared__ float rv[256];
    __shared__ int   ri[256];
    const float* z = g_zin + (long)tok * WIDTH;
    for (int i = tid; i < WIDTH; i += 256) { vals[i] = z[i]; sel[i] = 0; }
    __syncthreads();
    for (int it = 0; it < KVAL; it++) {
        float bm = -1e30f; int bi = WIDTH;
        for (int i = tid; i < WIDTH; i += 256) {
            if (!sel[i]) {
                float x = vals[i];
                if (x > bm) { bm = x; bi = i; }
            }
        }
        rv[tid] = bm; ri[tid] = bi; __syncthreads();
        for (int o = 128; o > 0; o >>= 1) {
            if (tid < o) {
                float xv = rv[tid+o]; int xi = ri[tid+o];
                if (xv > rv[tid] || (xv == rv[tid] && xi < ri[tid])) { rv[tid] = xv; ri[tid] = xi; }
            }
            __syncthreads();
        }
        if (tid == 0) {
            g_tkv[tok*KVAL + it] = rv[0];
            g_tki[tok*KVAL + it] = ri[0];
            sel[ri[0]] = 1;
        }
        __syncthreads();
    }
}

// out = proj * Dz + b + sum_j tkv[j] * D[tki[j], :]   ; one block per token
__global__ void final_kernel(const float* __restrict__ D, const float* __restrict__ b,
                             float* __restrict__ out)
{
    const int tok = blockIdx.x, tid = threadIdx.x;  // 256
    __shared__ float v[KVAL];
    __shared__ int   id[KVAL];
    if (tid < KVAL) { v[tid] = g_tkv[tok*KVAL + tid]; id[tid] = g_tki[tok*KVAL + tid]; }
    __syncthreads();
    const float p = g_proj[tok];
    for (int n = tid; n < DIMIN; n += 256) {
        float a = p * g_Dz[(long)tok*DIMIN + n] + b[n];
        #pragma unroll 8
        for (int j = 0; j < KVAL; j++)
            a += v[j] * D[(long)id[j]*DIMIN + n];
        out[(long)tok*DIMIN + n] = a;
    }
}

// ---------------- host launch ----------------
extern "C" void kernel_launch(void* const* d_in, const int* in_sizes, int n_in,
                              void* d_out, int out_size)
{
    const float* x_input = (const float*)d_in[0];
    const float* D       = (const float*)d_in[1];
    const float* b       = (const float*)d_in[2];
    const float* Wk      = (const float*)d_in[3];
    const float* bk      = (const float*)d_in[4];
    const float* Wq      = (const float*)d_in[5];
    const float* bq      = (const float*)d_in[6];
    const float* Wv      = (const float*)d_in[7];
    const float* bv      = (const float*)d_in[8];
    const float* Wo      = (const float*)d_in[9];
    const float* bo      = (const float*)d_in[10];
    float* out = (float*)d_out;

    void *px, *px2, *pzin, *pzctx, *pq, *pk, *pv, *patt, *po, *pzp, *pdz;
    cudaGetSymbolAddress(&px,    g_x);
    cudaGetSymbolAddress(&px2,   g_x2);
    cudaGetSymbolAddress(&pzin,  g_zin);
    cudaGetSymbolAddress(&pzctx, g_zctx);
    cudaGetSymbolAddress(&pq,    g_q);
    cudaGetSymbolAddress(&pk,    g_k);
    cudaGetSymbolAddress(&pv,    g_v);
    cudaGetSymbolAddress(&patt,  g_att);
    cudaGetSymbolAddress(&po,    g_o);
    cudaGetSymbolAddress(&pzp,   g_zp);
    cudaGetSymbolAddress(&pdz,   g_Dz);

    // 1) x = x_input - b
    sub_b_kernel<<<(NTOK*DIMIN)/256, 256>>>(x_input, b);

    // 2) z_in = relu(lam * x @ D^T)     M=4096 N=8192 K=768
    {
        dim3 g(WIDTH/BN, NTOK/BM, 1);
        sgemm_kernel<0,true,false><<<g,256>>>((const float*)px, D, (float*)pzin, nullptr,
            DIMIN, DIMIN, DIMIN, WIDTH, LAM, 0,0,0,0,0,1);
    }
    // 3) z_ctx = shift(z_in)
    shift_kernel<<<(int)(((long)NTOK*WIDTH)/256), 256>>>();

    // 4) q = z_in @ Wq^T + bq           M=4096 N=128 K=8192
    {
        dim3 g(NEMBDS/BN, NTOK/BM, 1);
        sgemm_kernel<0,false,true><<<g,256>>>((const float*)pzin, Wq, (float*)pq, bq,
            WIDTH, WIDTH, WIDTH, NEMBDS, 1.0f, 0,0,0,0,0,1);
        sgemm_kernel<0,false,true><<<g,256>>>((const float*)pzctx, Wk, (float*)pk, bk,
            WIDTH, WIDTH, WIDTH, NEMBDS, 1.0f, 0,0,0,0,0,1);
    }
    // 5) v = z_ctx @ Wv^T + bv          M=4096 N=8192 K=8192
    {
        dim3 g(WIDTH/BN, NTOK/BM, 1);
        sgemm_kernel<0,false,true><<<g,256>>>((const float*)pzctx, Wv, (float*)pv, bv,
            WIDTH, WIDTH, WIDTH, WIDTH, 1.0f, 0,0,0,0,0,1);
    }
    // 6) causal softmax scores
    {
        dim3 g(TSEQ, NBATCH*NHEADS, 1);
        attn_softmax_kernel<<<g, 128>>>();
    }
    // 7) o = a @ v (batched per (b,h))  M=512 N=1024 K=512, z=64
    {
        dim3 g(DHV/BN, TSEQ/BM, NBATCH*NHEADS);
        sgemm_kernel<1,false,false><<<g,256>>>((const float*)patt, (const float*)pv, (float*)po, nullptr,
            TSEQ, TSEQ, WIDTH, WIDTH, 1.0f,
            (long)TSEQ*TSEQ,                 // A stride per z
            (long)TSEQ*WIDTH, (long)DHV,     // B: per-batch, per-head
            (long)TSEQ*WIDTH, (long)DHV,     // C: same
            NHEADS);
    }
    // 8) z_pred_ = relu(o @ Wo^T + bo)  M=4096 N=8192 K=8192
    {
        dim3 g(WIDTH/BN, NTOK/BM, 1);
        sgemm_kernel<0,true,true><<<g,256>>>((const float*)po, Wo, (float*)pzp, bo,
            WIDTH, WIDTH, WIDTH, WIDTH, 1.0f, 0,0,0,0,0,1);
    }
    // 9) Dz = z_pred_ @ D               M=4096 N=768 K=8192 (NN)
    {
        dim3 g(DIMIN/BN, NTOK/BM, 1);
        sgemm_kernel<1,false,false><<<g,256>>>((const float*)pzp, D, (float*)pdz, nullptr,
            WIDTH, WIDTH, DIMIN, DIMIN, 1.0f, 0,0,0,0,0,1);
    }
    // 10) proj + x2
    proj_kernel<<<NTOK, 256>>>();

    // 11) z_novel = relu(lam * x2 @ D^T) -> g_zin (reuse)
    {
        dim3 g(WIDTH/BN, NTOK/BM, 1);
        sgemm_kernel<0,true,false><<<g,256>>>((const float*)px2, D, (float*)pzin, nullptr,
            DIMIN, DIMIN, DIMIN, WIDTH, LAM, 0,0,0,0,0,1);
    }
    // 12) top-32 per token
    topk_kernel<<<NTOK, 256>>>();

    // 13) out = proj*Dz + b + sparse(z_novel)@D
    final_kernel<<<NTOK, 256>>>(D, b, out);
}

// round 8
// speedup vs baseline: 3.6872x; 3.6872x over previous
#include <cuda_runtime.h>
#include <cuda_bf16.h>
#include <cstdint>
#include <math.h>

// ---------------- problem constants ----------------
#define NTOK   4096      // B*T
#define TSEQ   512
#define NBATCH 8
#define DIMIN  768
#define WIDTH  8192
#define NHEADS 8
#define NEMBDS 128
#define DHQK   16
#define DHV    1024
#define KVAL   32
#define LAM    (1.0f/3072.0f)   // 1/(4*DIMIN)

// tcgen05 is only legal in arch-SPECIFIC (sm_103a) compilation passes.
// The harness also builds a plain sm_103 pass; give that pass a SIMT body.
#if defined(__CUDA_ARCH_FEAT_SM103_ALL) || defined(__CUDA_ARCH_FEAT_SM100_ALL) || defined(__CUDA_ARCH_SPECIFIC__)
#define TC_OK 1
#else
#define TC_OK 0
#endif

// ---------------- scratch (device globals; no allocation allowed) ----------------
__device__ float g_x   [NTOK*DIMIN];
__device__ float g_x2  [NTOK*DIMIN];
__device__ float g_zin [(size_t)NTOK*WIDTH];   // reused for z_novel
__device__ float g_zctx[(size_t)NTOK*WIDTH];
__device__ float g_q   [NTOK*NEMBDS];
__device__ float g_k   [NTOK*NEMBDS];
__device__ float g_v   [(size_t)NTOK*WIDTH];
__device__ float g_att [(size_t)NBATCH*NHEADS*TSEQ*TSEQ];
__device__ float g_o   [(size_t)NTOK*WIDTH];
__device__ float g_zp  [(size_t)NTOK*WIDTH];
__device__ float g_Dz  [NTOK*DIMIN];
__device__ float g_Dt  [DIMIN*WIDTH];          // D^T fp32 (for Dz GEMM)
__device__ float g_proj[NTOK];
__device__ float g_tkv [NTOK*KVAL];
__device__ int   g_tki [NTOK*KVAL];

// =====================================================================
// GEMM:  C[M,N] = alpha * (A[M,K] @ B[N,K]^T) (+bias)(+relu)
// A fp32 row-major [M,K]; B fp32 row-major [N,K] (weight layout).
// sm_103a pass: tcgen05 split-bf16 (hi/lo), 128x128x64 tiles, TMEM acc.
// plain pass:   SIMT fp32 fallback (8x8 microtile).
// =====================================================================
#define GBK 64
#define PLANE_BYTES 16384          // 128 rows x 64 bf16 (128B/row, SW128)
#define STAGE_BYTES (4*PLANE_BYTES)
#define TG_DSMEM (2*STAGE_BYTES + 1024 + 64)

__device__ __forceinline__ uint32_t smem_addr_u32(const void* p) {
    uint32_t a;
    asm("{ .reg .u64 t; cvta.to.shared.u64 t, %1; cvt.u32.u64 %0, t; }" : "=r"(a) : "l"(p));
    return a;
}

#if TC_OK
// SW128 K-major SMEM descriptor (version=1, layout=2, SBO=64, LBO=1)
__device__ __forceinline__ uint64_t mk_desc(uint32_t addr) {
    return ((uint64_t)2 << 61) | ((uint64_t)1 << 46) | ((uint64_t)64 << 32)
         | ((uint64_t)1 << 16) | ((uint64_t)((addr >> 4) & 0x3FFF));
}

__device__ __forceinline__ void mma_f16_ss(uint32_t d, uint64_t a, uint64_t b,
                                           uint32_t idesc, uint32_t en) {
    asm volatile(
        "{\n\t.reg .pred p;\n\tsetp.ne.u32 p, %4, 0;\n\t"
        "tcgen05.mma.cta_group::1.kind::f16 [%0], %1, %2, %3, {%5,%5,%5,%5}, p;\n\t}"
        :: "r"(d), "l"(a), "l"(b), "r"(idesc), "r"(en), "r"(0u) : "memory");
}

#define MBAR_INIT(a, c) \
    asm volatile("mbarrier.init.shared.b64 [%0], %1;" :: "r"(a), "r"(c) : "memory")

#define MBAR_WAIT(mbar, par) do { \
    uint32_t _m = (mbar); uint32_t _p = (par); uint32_t _done; \
    asm volatile("{\n\t.reg .pred p;\n\t" \
        "mbarrier.try_wait.parity.acquire.cta.shared::cta.b64 p, [%1], %2;\n\t" \
        "selp.b32 %0, 1, 0, p;\n\t}" : "=r"(_done) : "r"(_m), "r"(_p) : "memory"); \
    if (!_done) { \
        asm volatile("{\n\t.reg .pred P1;\n\tWL_%=:\n\t" \
            "mbarrier.try_wait.parity.acquire.cta.shared::cta.b64 P1, [%0], %1, 0x989680;\n\t" \
            "@P1 bra.uni WD_%=;\n\tbra.uni WL_%=;\n\tWD_%=:\n\t}" \
            :: "r"(_m), "r"(_p) : "memory"); \
    } \
} while (0)

#define LDTM_X32(r, ta) \
    asm volatile("tcgen05.ld.sync.aligned.32x32b.x32.b32 " \
        "{%0,%1,%2,%3,%4,%5,%6,%7,%8,%9,%10,%11,%12,%13,%14,%15," \
        "%16,%17,%18,%19,%20,%21,%22,%23,%24,%25,%26,%27,%28,%29,%30,%31}, [%32];" \
        : "=r"((r)[0]),"=r"((r)[1]),"=r"((r)[2]),"=r"((r)[3]), \
          "=r"((r)[4]),"=r"((r)[5]),"=r"((r)[6]),"=r"((r)[7]), \
          "=r"((r)[8]),"=r"((r)[9]),"=r"((r)[10]),"=r"((r)[11]), \
          "=r"((r)[12]),"=r"((r)[13]),"=r"((r)[14]),"=r"((r)[15]), \
          "=r"((r)[16]),"=r"((r)[17]),"=r"((r)[18]),"=r"((r)[19]), \
          "=r"((r)[20]),"=r"((r)[21]),"=r"((r)[22]),"=r"((r)[23]), \
          "=r"((r)[24]),"=r"((r)[25]),"=r"((r)[26]),"=r"((r)[27]), \
          "=r"((r)[28]),"=r"((r)[29]),"=r"((r)[30]),"=r"((r)[31]) \
        : "r"(ta))

// load a 128x64 fp32 tile, split to hi/lo bf16 planes, store swizzled to SMEM
// 256 threads: 8 iterations of one float4 each.
__device__ __forceinline__ void ldsplit(const float* __restrict__ G, int ld, int rowbase,
                                        int kcol0, uint32_t sH, uint32_t sL)
{
    const int tid = threadIdx.x;
    #pragma unroll
    for (int j = 0; j < 8; j++) {
        int idx = j*256 + tid;
        int row = idx >> 4, c4 = idx & 15;
        const float4 v = *(const float4*)(G + (size_t)(rowbase+row)*ld + kcol0 + c4*4);
        __nv_bfloat162 h01 = __floats2bfloat162_rn(v.x, v.y);
        __nv_bfloat162 h23 = __floats2bfloat162_rn(v.z, v.w);
        float2 f01 = __bfloat1622float2(h01);
        float2 f23 = __bfloat1622float2(h23);
        __nv_bfloat162 l01 = __floats2bfloat162_rn(v.x - f01.x, v.y - f01.y);
        __nv_bfloat162 l23 = __floats2bfloat162_rn(v.z - f23.x, v.w - f23.y);
        uint32_t off = row*128 + c4*8;
        uint32_t sw  = off ^ ((off >> 3) & 0x70);
        unsigned uh01 = *reinterpret_cast<unsigned*>(&h01);
        unsigned uh23 = *reinterpret_cast<unsigned*>(&h23);
        unsigned ul01 = *reinterpret_cast<unsigned*>(&l01);
        unsigned ul23 = *reinterpret_cast<unsigned*>(&l23);
        asm volatile("st.shared.v2.b32 [%0], {%1,%2};" :: "r"(sH + sw), "r"(uh01), "r"(uh23));
        asm volatile("st.shared.v2.b32 [%0], {%1,%2};" :: "r"(sL + sw), "r"(ul01), "r"(ul23));
    }
}
#endif  // TC_OK

template<bool RELU, bool HASB>
__global__ void __launch_bounds__(256, 1) tgemm(
    const float* __restrict__ Ag, const float* __restrict__ Bg,
    float* __restrict__ Cg, const float* __restrict__ bias,
    int K, int N, int MT, int NT, float alpha,
    const float* Ag2, const float* Bg2, float* Cg2, const float* bias2)
{
    if (blockIdx.y == 1) { Ag = Ag2; Bg = Bg2; Cg = Cg2; bias = bias2; }

    extern __shared__ char smem[];
    const int tid = threadIdx.x;

    // L2-friendly rasterization: groups of 8 N-tiles, M-major inside group
    int bid = blockIdx.x;
    const int GW = 8;
    int tpg = MT * GW;
    int g = bid / tpg, r = bid % tpg;
    int n0 = g * GW;
    int gw = NT - n0; if (gw > GW) gw = GW;
    const int bm = (r / gw) * 128;
    const int bn = (n0 + r % gw) * 128;

#if TC_OK
    uint32_t SB   = (smem_addr_u32(smem) + 1023u) & ~1023u;
    uint32_t ctrl = SB + 2*STAGE_BYTES;   // [ctrl]=tmem ptr, [ctrl+16/+24]=mbar[0/1]

    if (tid < 32) {
        asm volatile("tcgen05.alloc.cta_group::1.sync.aligned.shared::cta.b32 [%0], %1;"
                     :: "r"(ctrl), "r"(128u) : "memory");
        asm volatile("tcgen05.relinquish_alloc_permit.cta_group::1.sync.aligned;");
    }
    if (tid == 0) { MBAR_INIT(ctrl+16, 1); MBAR_INIT(ctrl+24, 1); }
    __syncthreads();
    uint32_t tmem;
    asm("ld.shared.b32 %0, [%1];" : "=r"(tmem) : "r"(ctrl));

    const uint32_t idesc = (1u<<4) | (1u<<7) | (1u<<10) | (16u<<17) | (8u<<24);
    const int KT = K / GBK;

    // prologue: tile 0 -> stage 0
    ldsplit(Ag, K, bm, 0, SB,                  SB +   PLANE_BYTES);
    ldsplit(Bg, K, bn, 0, SB + 2*PLANE_BYTES,  SB + 3*PLANE_BYTES);
    __syncthreads();

    int ph0 = 0, ph1 = 0;
    for (int kt = 0; kt < KT; ++kt) {
        const int s = kt & 1;
        if (tid == 0) {
            asm volatile("fence.proxy.async.shared::cta;" ::: "memory");
            uint32_t base = SB + s*STAGE_BYTES;
            uint64_t dAh = mk_desc(base);
            uint64_t dAl = mk_desc(base +   PLANE_BYTES);
            uint64_t dBh = mk_desc(base + 2*PLANE_BYTES);
            uint64_t dBl = mk_desc(base + 3*PLANE_BYTES);
            uint32_t en = (kt > 0) ? 1u : 0u;
            #pragma unroll
            for (int st = 0; st < 4; ++st) {
                uint64_t o = 2*st;     // 16 bf16 = 32B = 2 x 16B units per K step
                mma_f16_ss(tmem, dAh + o, dBh + o, idesc, en); en = 1u;
                mma_f16_ss(tmem, dAh + o, dBl + o, idesc, 1u);
                mma_f16_ss(tmem, dAl + o, dBh + o, idesc, 1u);
            }
            asm volatile("tcgen05.commit.cta_group::1.mbarrier::arrive::one.shared::cluster.b64 [%0];"
                         :: "r"(ctrl + 16 + 8*s) : "memory");
            if (kt >= 1 && kt + 1 < KT) {      // free the other stage
                int so = s ^ 1;
                if (so) { MBAR_WAIT(ctrl+24, ph1); ph1 ^= 1; }
                else    { MBAR_WAIT(ctrl+16, ph0); ph0 ^= 1; }
            }
        }
        __syncthreads();
        if (kt + 1 < KT) {
            uint32_t base = SB + (s^1)*STAGE_BYTES;
            ldsplit(Ag, K, bm, (kt+1)*GBK, base,                 base +   PLANE_BYTES);
            ldsplit(Bg, K, bn, (kt+1)*GBK, base + 2*PLANE_BYTES, base + 3*PLANE_BYTES);
        }
        __syncthreads();
    }
    if (tid == 0) {
        int sl = (KT-1) & 1;
        if (sl) { MBAR_WAIT(ctrl+24, ph1); }
        else    { MBAR_WAIT(ctrl+16, ph0); }
    }
    __syncthreads();
    asm volatile("tcgen05.fence::after_thread_sync;" ::: "memory");

    // epilogue: TMEM -> fp32 C (warps 0-3)
    if (tid < 128) {
        const int wid = tid >> 5, lane = tid & 31;
        const int row = bm + wid*32 + lane;
        #pragma unroll
        for (int cb = 0; cb < 128; cb += 32) {
            uint32_t rr[32];
            LDTM_X32(rr, tmem + cb);
            asm volatile("tcgen05.wait::ld.sync.aligned;" ::: "memory");
            float* crow = Cg + (size_t)row*N + bn + cb;
            #pragma unroll
            for (int q4 = 0; q4 < 8; q4++) {
                float4 o4;
                float vv[4];
                #pragma unroll
                for (int t = 0; t < 4; t++) {
                    float v = alpha * __uint_as_float(rr[q4*4 + t]);
                    if (HASB) v += bias[bn + cb + q4*4 + t];
                    if (RELU) v = fmaxf(v, 0.f);
                    vv[t] = v;
                }
                o4.x = vv[0]; o4.y = vv[1]; o4.z = vv[2]; o4.w = vv[3];
                *(float4*)(crow + q4*4) = o4;
            }
        }
    }
    __syncthreads();
    if (tid < 32) {
        asm volatile("tcgen05.dealloc.cta_group::1.sync.aligned.b32 %0, %1;"
                     :: "r"(tmem), "r"(128u));
    }
#else
    // ---------- SIMT fp32 fallback (correct on any pass; perf irrelevant if
    // the sm_103a cubin is the one loaded) ----------
    float (*As)[128] = (float(*)[128])smem;                  // [8][128]
    float (*Bs)[128] = (float(*)[128])(smem + 8*128*4);      // [8][128]

    const int tr = tid >> 4, tc = tid & 15;
    const int lr = tid >> 1, lc = (tid & 1) * 4;

    float acc[8][8];
    #pragma unroll
    for (int i = 0; i < 8; i++)
        #pragma unroll
        for (int j = 0; j < 8; j++) acc[i][j] = 0.f;

    const float* Aptr  = Ag + (size_t)(bm + lr) * K + lc;
    const float* BptrW = Bg + (size_t)(bn + lr) * K + lc;

    for (int k0 = 0; k0 < K; k0 += 8) {
        float4 a4 = *(const float4*)(Aptr + k0);
        As[lc+0][lr] = a4.x; As[lc+1][lr] = a4.y;
        As[lc+2][lr] = a4.z; As[lc+3][lr] = a4.w;
        float4 b4 = *(const float4*)(BptrW + k0);
        Bs[lc+0][lr] = b4.x; Bs[lc+1][lr] = b4.y;
        Bs[lc+2][lr] = b4.z; Bs[lc+3][lr] = b4.w;
        __syncthreads();
        #pragma unroll
        for (int kk = 0; kk < 8; kk++) {
            float ra[8], rb[8];
            *(float4*)(ra)   = *(const float4*)&As[kk][tr*8];
            *(float4*)(ra+4) = *(const float4*)&As[kk][tr*8+4];
            *(float4*)(rb)   = *(const float4*)&Bs[kk][tc*8];
            *(float4*)(rb+4) = *(const float4*)&Bs[kk][tc*8+4];
            #pragma unroll
            for (int i = 0; i < 8; i++)
                #pragma unroll
                for (int j = 0; j < 8; j++)
                    acc[i][j] += ra[i] * rb[j];
        }
        __syncthreads();
    }
    #pragma unroll
    for (int i = 0; i < 8; i++) {
        float* crow = Cg + (size_t)(bm + tr*8 + i) * N + bn + tc*8;
        #pragma unroll
        for (int jj = 0; jj < 8; jj += 4) {
            float4 o4;
            float vv[4];
            #pragma unroll
            for (int t = 0; t < 4; t++) {
                float v = alpha * acc[i][jj+t];
                if (HASB) v += bias[bn + tc*8 + jj + t];
                if (RELU) v = fmaxf(v, 0.f);
                vv[t] = v;
            }
            o4.x = vv[0]; o4.y = vv[1]; o4.z = vv[2]; o4.w = vv[3];
            *(float4*)(crow + jj) = o4;
        }
    }
#endif
}

// ---------------- SIMT fp32 GEMM (attention a @ v only) ----------------
#define BM 128
#define BN 128
#define BKS 8
__global__ void __launch_bounds__(256) sgemm_nn_kernel(
    const float* __restrict__ Ag, const float* __restrict__ Bg,
    float* __restrict__ Cg,
    int K, int lda, int ldb, int ldc,
    long sA, long sB1, long sB2, long sC1, long sC2, int zdiv)
{
    {
        int z = blockIdx.z;
        int zb = z / zdiv, zh = z % zdiv;
        Ag += (long)z * sA;
        Bg += (long)zb * sB1 + (long)zh * sB2;
        Cg += (long)zb * sC1 + (long)zh * sC2;
    }
    __shared__ float As[BKS][BM];
    __shared__ float Bs[BKS][BN];
    const int tid = threadIdx.x;
    const int bm = blockIdx.y * BM;
    const int bn = blockIdx.x * BN;
    const int tr = tid >> 4, tc = tid & 15;
    const int lr = tid >> 1, lc = (tid & 1) * 4;
    const int nr = tid >> 5, nc = (tid & 31) * 4;

    float acc[8][8];
    #pragma unroll
    for (int i = 0; i < 8; i++)
        #pragma unroll
        for (int j = 0; j < 8; j++) acc[i][j] = 0.f;

    const float* Aptr  = Ag + (long)(bm + lr) * lda + lc;
    const float* BptrN = Bg + (long)nr * ldb + bn + nc;

    for (int k0 = 0; k0 < K; k0 += BKS) {
        float4 a4 = *(const float4*)(Aptr + k0);
        As[lc+0][lr] = a4.x; As[lc+1][lr] = a4.y;
        As[lc+2][lr] = a4.z; As[lc+3][lr] = a4.w;
        float4 b4 = *(const float4*)(BptrN + (long)k0 * ldb);
        *(float4*)&Bs[nr][nc] = b4;
        __syncthreads();
        #pragma unroll
        for (int kk = 0; kk < BKS; kk++) {
            float ra[8], rb[8];
            *(float4*)(ra)   = *(const float4*)&As[kk][tr*8];
            *(float4*)(ra+4) = *(const float4*)&As[kk][tr*8+4];
            *(float4*)(rb)   = *(const float4*)&Bs[kk][tc*8];
            *(float4*)(rb+4) = *(const float4*)&Bs[kk][tc*8+4];
            #pragma unroll
            for (int i = 0; i < 8; i++)
                #pragma unroll
                for (int j = 0; j < 8; j++)
                    acc[i][j] += ra[i] * rb[j];
        }
        __syncthreads();
    }
    #pragma unroll
    for (int i = 0; i < 8; i++) {
        float* crow = Cg + (long)(bm + tr*8 + i) * ldc + bn + tc*8;
        #pragma unroll
        for (int jj = 0; jj < 8; jj += 4) {
            float4 o4;
            o4.x = acc[i][jj+0]; o4.y = acc[i][jj+1];
            o4.z = acc[i][jj+2]; o4.w = acc[i][jj+3];
            *(float4*)(crow + jj) = o4;
        }
    }
}

// ---------------- elementwise / glue kernels ----------------
__global__ void sub_b_kernel(const float* __restrict__ xin, const float* __restrict__ b)
{
    int i = blockIdx.x * 256 + threadIdx.x;
    g_x[i] = xin[i] - b[i % DIMIN];
}

__global__ void transpose_kernel(const float* __restrict__ D)  // -> g_Dt [DIMIN, WIDTH]
{
    __shared__ float t[32][33];
    int bx = blockIdx.x * 32;   // over DIMIN
    int by = blockIdx.y * 32;   // over WIDTH
    int x = threadIdx.x, y = threadIdx.y;  // 32 x 8
    #pragma unroll
    for (int i = 0; i < 32; i += 8)
        t[y+i][x] = D[(size_t)(by + y + i) * DIMIN + bx + x];
    __syncthreads();
    #pragma unroll
    for (int i = 0; i < 32; i += 8)
        g_Dt[(size_t)(bx + y + i) * WIDTH + by + x] = t[x][y+i];
}

__global__ void shift_kernel()
{
    long i = (long)blockIdx.x * 256 + threadIdx.x;
    long tok = i >> 13;
    int  t   = (int)(tok & (TSEQ-1));
    g_zctx[i] = (t == 0) ? 0.f : g_zin[i - WIDTH];
}

__global__ void attn_softmax_kernel()
{
    const int t  = blockIdx.x;
    const int bh = blockIdx.y;
    const int b  = bh >> 3, h = bh & 7;
    __shared__ float qs[DHQK];
    __shared__ float sc[TSEQ];
    __shared__ float red[128];
    const int tid = threadIdx.x;

    if (tid < DHQK) qs[tid] = g_q[(long)(b*TSEQ + t)*NEMBDS + h*DHQK + tid];
    __syncthreads();

    float lmax = -1e30f;
    for (int s = tid; s < TSEQ; s += 128) {
        float val = -1e30f;
        if (s <= t) {
            const float* kp = g_k + (long)(b*TSEQ + s)*NEMBDS + h*DHQK;
            float d = 0.f;
            #pragma unroll
            for (int i = 0; i < DHQK; i++) d += qs[i] * kp[i];
            val = d * 0.25f;
        }
        sc[s] = val;
        lmax = fmaxf(lmax, val);
    }
    red[tid] = lmax; __syncthreads();
    for (int o = 64; o > 0; o >>= 1) { if (tid < o) red[tid] = fmaxf(red[tid], red[tid+o]); __syncthreads(); }
    const float mx = red[0];
    __syncthreads();
    float lsum = 0.f;
    for (int s = tid; s < TSEQ; s += 128) {
        float e = (s <= t) ? expf(sc[s] - mx) : 0.f;
        sc[s] = e; lsum += e;
    }
    red[tid] = lsum; __syncthreads();
    for (int o = 64; o > 0; o >>= 1) { if (tid < o) red[tid] += red[tid+o]; __syncthreads(); }
    const float inv = 1.f / red[0];
    float* ap = g_att + ((long)bh * TSEQ + t) * TSEQ;
    for (int s = tid; s < TSEQ; s += 128) ap[s] = sc[s] * inv;
}

__global__ void proj_kernel()
{
    const int tok = blockIdx.x, tid = threadIdx.x;
    const float* dz = g_Dz + (long)tok * DIMIN;
    const float* xx = g_x  + (long)tok * DIMIN;
    float d1 = 0.f, d2 = 0.f;
    for (int i = tid; i < DIMIN; i += 256) { float a = dz[i]; d1 += a * xx[i]; d2 += a * a; }
    __shared__ float r1[256], r2[256];
    r1[tid] = d1; r2[tid] = d2; __syncthreads();
    for (int o = 128; o > 0; o >>= 1) { if (tid < o) { r1[tid] += r1[tid+o]; r2[tid] += r2[tid+o]; } __syncthreads(); }
    const float p = r1[0] / (r2[0] + 1e-6f);
    if (tid == 0) g_proj[tok] = p;
    for (int i = tid; i < DIMIN; i += 256)
        g_x2[(long)tok*DIMIN + i] = xx[i] - p * dz[i];
}

__global__ void topk_kernel()
{
    const int tok = blockIdx.x, tid = threadIdx.x;
    __shared__ float vals[WIDTH];
    __shared__ unsigned char sel[WIDTH];
    __shared__ float rv[256];
    __shared__ int   ri[256];
    const float* z = g_zin + (long)tok * WIDTH;
    for (int i = tid; i < WIDTH; i += 256) { vals[i] = z[i]; sel[i] = 0; }
    __syncthreads();
    for (int it = 0; it < KVAL; it++) {
        float bm2 = -1e30f; int bi = WIDTH;
        for (int i = tid; i < WIDTH; i += 256) {
            if (!sel[i]) {
                float x = vals[i];
                if (x > bm2) { bm2 = x; bi = i; }
            }
        }
        rv[tid] = bm2; ri[tid] = bi; __syncthreads();
        for (int o = 128; o > 0; o >>= 1) {
            if (tid < o) {
                float xv = rv[tid+o]; int xi = ri[tid+o];
                if (xv > rv[tid] || (xv == rv[tid] && xi < ri[tid])) { rv[tid] = xv; ri[tid] = xi; }
            }
            __syncthreads();
        }
        if (tid == 0) {
            g_tkv[tok*KVAL + it] = rv[0];
            g_tki[tok*KVAL + it] = ri[0];
            sel[ri[0]] = 1;
        }
        __syncthreads();
    }
}

__global__ void final_kernel(const float* __restrict__ D, const float* __restrict__ b,
                             float* __restrict__ out)
{
    const int tok = blockIdx.x, tid = threadIdx.x;
    __shared__ float v[KVAL];
    __shared__ int   id[KVAL];
    if (tid < KVAL) { v[tid] = g_tkv[tok*KVAL + tid]; id[tid] = g_tki[tok*KVAL + tid]; }
    __syncthreads();
    const float p = g_proj[tok];
    for (int n = tid; n < DIMIN; n += 256) {
        float a = p * g_Dz[(long)tok*DIMIN + n] + b[n];
        #pragma unroll 8
        for (int j = 0; j < KVAL; j++)
            a += v[j] * D[(long)id[j]*DIMIN + n];
        out[(long)tok*DIMIN + n] = a;
    }
}

// ---------------- host launch ----------------
extern "C" void kernel_launch(void* const* d_in, const int* in_sizes, int n_in,
                              void* d_out, int out_size)
{
    const float* x_input = (const float*)d_in[0];
    const float* D       = (const float*)d_in[1];
    const float* b       = (const float*)d_in[2];
    const float* Wk      = (const float*)d_in[3];
    const float* bk      = (const float*)d_in[4];
    const float* Wq      = (const float*)d_in[5];
    const float* bq      = (const float*)d_in[6];
    const float* Wv      = (const float*)d_in[7];
    const float* bv      = (const float*)d_in[8];
    const float* Wo      = (const float*)d_in[9];
    const float* bo      = (const float*)d_in[10];
    float* out = (float*)d_out;

    void *px, *px2, *pzin, *pzctx, *pq, *pk, *pv, *patt, *po, *pzp, *pdz, *pdt;
    cudaGetSymbolAddress(&px,    g_x);
    cudaGetSymbolAddress(&px2,   g_x2);
    cudaGetSymbolAddress(&pzin,  g_zin);
    cudaGetSymbolAddress(&pzctx, g_zctx);
    cudaGetSymbolAddress(&pq,    g_q);
    cudaGetSymbolAddress(&pk,    g_k);
    cudaGetSymbolAddress(&pv,    g_v);
    cudaGetSymbolAddress(&patt,  g_att);
    cudaGetSymbolAddress(&po,    g_o);
    cudaGetSymbolAddress(&pzp,   g_zp);
    cudaGetSymbolAddress(&pdz,   g_Dz);
    cudaGetSymbolAddress(&pdt,   g_Dt);

    cudaFuncSetAttribute(tgemm<false,false>, cudaFuncAttributeMaxDynamicSharedMemorySize, TG_DSMEM);
    cudaFuncSetAttribute(tgemm<false,true >, cudaFuncAttributeMaxDynamicSharedMemorySize, TG_DSMEM);
    cudaFuncSetAttribute(tgemm<true ,false>, cudaFuncAttributeMaxDynamicSharedMemorySize, TG_DSMEM);
    cudaFuncSetAttribute(tgemm<true ,true >, cudaFuncAttributeMaxDynamicSharedMemorySize, TG_DSMEM);

    // 1) x = x_input - b ; D^T
    sub_b_kernel<<<(NTOK*DIMIN)/256, 256>>>(x_input, b);
    transpose_kernel<<<dim3(DIMIN/32, WIDTH/32), dim3(32,8)>>>(D);

    // 2) z_in = relu(lam * x @ D^T)   M=4096 N=8192 K=768
    tgemm<true,false><<<dim3(32*64,1), 256, TG_DSMEM>>>(
        (const float*)px, D, (float*)pzin, nullptr,
        DIMIN, WIDTH, 32, 64, LAM, nullptr, nullptr, nullptr, nullptr);

    // 3) z_ctx = shift(z_in)
    shift_kernel<<<(int)(((long)NTOK*WIDTH)/256), 256>>>();

    // 4) q = z_in @ Wq^T + bq ; k = z_ctx @ Wk^T + bk   (batched via grid.y)
    tgemm<false,true><<<dim3(32*1,2), 256, TG_DSMEM>>>(
        (const float*)pzin, Wq, (float*)pq, bq,
        WIDTH, NEMBDS, 32, 1, 1.0f,
        (const float*)pzctx, Wk, (float*)pk, bk);

    // 5) v = z_ctx @ Wv^T + bv        M=4096 N=8192 K=8192
    tgemm<false,true><<<dim3(32*64,1), 256, TG_DSMEM>>>(
        (const float*)pzctx, Wv, (float*)pv, bv,
        WIDTH, WIDTH, 32, 64, 1.0f, nullptr, nullptr, nullptr, nullptr);

    // 6) causal softmax
    attn_softmax_kernel<<<dim3(TSEQ, NBATCH*NHEADS), 128>>>();

    // 7) o = a @ v (fp32 SIMT, batched per (b,h))
    {
        dim3 g(DHV/BN, TSEQ/BM, NBATCH*NHEADS);
        sgemm_nn_kernel<<<g, 256>>>((const float*)patt, (const float*)pv, (float*)po,
            TSEQ, TSEQ, WIDTH, WIDTH,
            (long)TSEQ*TSEQ, (long)TSEQ*WIDTH, (long)DHV,
            (long)TSEQ*WIDTH, (long)DHV, NHEADS);
    }

    // 8) z_pred_ = relu(o @ Wo^T + bo)
    tgemm<true,true><<<dim3(32*64,1), 256, TG_DSMEM>>>(
        (const float*)po, Wo, (float*)pzp, bo,
        WIDTH, WIDTH, 32, 64, 1.0f, nullptr, nullptr, nullptr, nullptr);

    // 9) Dz = z_pred_ @ D  (= z_pred_ @ (D^T)^T)   N=768 K=8192
    tgemm<false,false><<<dim3(32*6,1), 256, TG_DSMEM>>>(
        (const float*)pzp, (const float*)pdt, (float*)pdz, nullptr,
        WIDTH, DIMIN, 32, 6, 1.0f, nullptr, nullptr, nullptr, nullptr);

    // 10) proj + x2
    proj_kernel<<<NTOK, 256>>>();

    // 11) z_novel = relu(lam * x2 @ D^T)
    tgemm<true,false><<<dim3(32*64,1), 256, TG_DSMEM>>>(
        (const float*)px2, D, (float*)pzin, nullptr,
        DIMIN, WIDTH, 32, 64, LAM, nullptr, nullptr, nullptr, nullptr);

    // 12) top-32 per token
    topk_kernel<<<NTOK, 256>>>();

    // 13) out = proj*Dz + b + sparse(z_novel)@D
    final_kernel<<<NTOK, 256>>>(D, b, out);
}

// round 10
// speedup vs baseline: 4.9073x; 1.3309x over previous
#include <cuda_runtime.h>
#include <cuda_bf16.h>
#include <cstdint>
#include <math.h>

// ---------------- problem constants ----------------
#define NTOK   4096      // B*T
#define TSEQ   512
#define NBATCH 8
#define DIMIN  768
#define WIDTH  8192
#define NHEADS 8
#define NEMBDS 128
#define DHQK   16
#define DHV    1024
#define KVAL   32
#define LAM    (1.0f/3072.0f)   // 1/(4*DIMIN)

#if defined(__CUDA_ARCH_FEAT_SM103_ALL) || defined(__CUDA_ARCH_FEAT_SM100_ALL) || defined(__CUDA_ARCH_SPECIFIC__)
#define TC_OK 1
#else
#define TC_OK 0
#endif

// ---------------- scratch (device globals; no allocation allowed) ----------------
__device__ float g_x   [NTOK*DIMIN];
__device__ float g_x2  [NTOK*DIMIN];
__device__ float g_zin [(size_t)NTOK*WIDTH];   // reused for z_novel
__device__ float g_q   [NTOK*NEMBDS];
__device__ float g_k   [NTOK*NEMBDS];
__device__ float g_v   [(size_t)NTOK*WIDTH];
__device__ float g_vT  [(size_t)NTOK*WIDTH];   // per-(b,h) transposed v
__device__ float g_att [(size_t)NBATCH*NHEADS*TSEQ*TSEQ];
__device__ float g_o   [(size_t)NTOK*WIDTH];
__device__ float g_zp  [(size_t)NTOK*WIDTH];
__device__ float g_Dz  [NTOK*DIMIN];
__device__ float g_Dt  [DIMIN*WIDTH];          // D^T fp32 (for Dz GEMM)
__device__ float g_proj[NTOK];
__device__ float g_tkv [NTOK*KVAL];
__device__ int   g_tki [NTOK*KVAL];

// =====================================================================
// tcgen05 split-bf16 GEMM:  C[M,N] = alpha*(A[M,K] @ B[N,K]^T)(+bias)(+relu)
// Tile 256x128, K-stage 64, SW128 swizzle (validated R8 encodings), 2-stage.
// M=256 as two independent 128-row MMA halves -> TMEM cols [0,128),[128,256).
// shiftA: A row r reads source row r-1 (zero when r % TSEQ == 0).
// =====================================================================
#define GBK 64
#define PLANE_BYTES 16384           // 128 rows x 64 bf16 (128B/row, SW128)
// stage: [Ah0][Al0][Ah1][Al1][Bh][Bl] = 6 planes = 96KB
#define STAGE_BYTES (6*PLANE_BYTES)
#define TG_DSMEM (2*STAGE_BYTES + 1024 + 64)

__device__ __forceinline__ uint32_t smem_addr_u32(const void* p) {
    uint32_t a;
    asm("{ .reg .u64 t; cvta.to.shared.u64 t, %1; cvt.u32.u64 %0, t; }" : "=r"(a) : "l"(p));
    return a;
}

#if TC_OK
// SW128 K-major SMEM descriptor (version=1, layout=2, SBO=64, LBO=1)
__device__ __forceinline__ uint64_t mk_desc(uint32_t addr) {
    return ((uint64_t)2 << 61) | ((uint64_t)1 << 46) | ((uint64_t)64 << 32)
         | ((uint64_t)1 << 16) | ((uint64_t)((addr >> 4) & 0x3FFF));
}

__device__ __forceinline__ void mma_f16_ss(uint32_t d, uint64_t a, uint64_t b,
                                           uint32_t idesc, uint32_t en) {
    asm volatile(
        "{\n\t.reg .pred p;\n\tsetp.ne.u32 p, %4, 0;\n\t"
        "tcgen05.mma.cta_group::1.kind::f16 [%0], %1, %2, %3, {%5,%5,%5,%5}, p;\n\t}"
        :: "r"(d), "l"(a), "l"(b), "r"(idesc), "r"(en), "r"(0u) : "memory");
}

#define MBAR_INIT(a, c) \
    asm volatile("mbarrier.init.shared.b64 [%0], %1;" :: "r"(a), "r"(c) : "memory")

#define MBAR_WAIT(mbar, par) do { \
    uint32_t _m = (mbar); uint32_t _p = (par); uint32_t _done; \
    asm volatile("{\n\t.reg .pred p;\n\t" \
        "mbarrier.try_wait.parity.acquire.cta.shared::cta.b64 p, [%1], %2;\n\t" \
        "selp.b32 %0, 1, 0, p;\n\t}" : "=r"(_done) : "r"(_m), "r"(_p) : "memory"); \
    if (!_done) { \
        asm volatile("{\n\t.reg .pred P1;\n\tWL_%=:\n\t" \
            "mbarrier.try_wait.parity.acquire.cta.shared::cta.b64 P1, [%0], %1, 0x989680;\n\t" \
            "@P1 bra.uni WD_%=;\n\tbra.uni WL_%=;\n\tWD_%=:\n\t}" \
            :: "r"(_m), "r"(_p) : "memory"); \
    } \
} while (0)

#define LDTM_X32(r, ta) \
    asm volatile("tcgen05.ld.sync.aligned.32x32b.x32.b32 " \
        "{%0,%1,%2,%3,%4,%5,%6,%7,%8,%9,%10,%11,%12,%13,%14,%15," \
        "%16,%17,%18,%19,%20,%21,%22,%23,%24,%25,%26,%27,%28,%29,%30,%31}, [%32];" \
        : "=r"((r)[0]),"=r"((r)[1]),"=r"((r)[2]),"=r"((r)[3]), \
          "=r"((r)[4]),"=r"((r)[5]),"=r"((r)[6]),"=r"((r)[7]), \
          "=r"((r)[8]),"=r"((r)[9]),"=r"((r)[10]),"=r"((r)[11]), \
          "=r"((r)[12]),"=r"((r)[13]),"=r"((r)[14]),"=r"((r)[15]), \
          "=r"((r)[16]),"=r"((r)[17]),"=r"((r)[18]),"=r"((r)[19]), \
          "=r"((r)[20]),"=r"((r)[21]),"=r"((r)[22]),"=r"((r)[23]), \
          "=r"((r)[24]),"=r"((r)[25]),"=r"((r)[26]),"=r"((r)[27]), \
          "=r"((r)[28]),"=r"((r)[29]),"=r"((r)[30]),"=r"((r)[31]) \
        : "r"(ta))

// load 128 rows x 64 k fp32, split hi/lo bf16, store SW128-swizzled.
// shiftTok: row r reads global row r-1; rows with (r % TSEQ)==0 are zero.
__device__ __forceinline__ void ldsplit(const float* __restrict__ G, int ld, int rowbase,
                                        int kcol0, uint32_t sH, uint32_t sL, int shiftTok)
{
    const int tid = threadIdx.x;
    #pragma unroll
    for (int j = 0; j < 8; j++) {
        int idx = j*256 + tid;
        int row = idx >> 4, c4 = idx & 15;
        int gr = rowbase + row;
        float4 v;
        if (shiftTok && ((gr & (TSEQ-1)) == 0)) {
            v.x = 0.f; v.y = 0.f; v.z = 0.f; v.w = 0.f;
        } else {
            v = *(const float4*)(G + (size_t)(gr - shiftTok)*ld + kcol0 + c4*4);
        }
        __nv_bfloat162 h01 = __floats2bfloat162_rn(v.x, v.y);
        __nv_bfloat162 h23 = __floats2bfloat162_rn(v.z, v.w);
        float2 f01 = __bfloat1622float2(h01);
        float2 f23 = __bfloat1622float2(h23);
        __nv_bfloat162 l01 = __floats2bfloat162_rn(v.x - f01.x, v.y - f01.y);
        __nv_bfloat162 l23 = __floats2bfloat162_rn(v.z - f23.x, v.w - f23.y);
        uint32_t off = row*128 + c4*8;
        uint32_t sw  = off ^ ((off >> 3) & 0x70);   // SW128
        unsigned uh01 = *reinterpret_cast<unsigned*>(&h01);
        unsigned uh23 = *reinterpret_cast<unsigned*>(&h23);
        unsigned ul01 = *reinterpret_cast<unsigned*>(&l01);
        unsigned ul23 = *reinterpret_cast<unsigned*>(&l23);
        asm volatile("st.shared.v2.b32 [%0], {%1,%2};" :: "r"(sH + sw), "r"(uh01), "r"(uh23));
        asm volatile("st.shared.v2.b32 [%0], {%1,%2};" :: "r"(sL + sw), "r"(ul01), "r"(ul23));
    }
}
#endif  // TC_OK

template<bool RELU, bool HASB>
__global__ void __launch_bounds__(256, 1) tgemm(
    const float* __restrict__ Ag, const float* __restrict__ Bg,
    float* __restrict__ Cg, const float* __restrict__ bias,
    int K, int ldc, int MT, int NT, float alpha, int shiftA,
    long sA, long sB, long sC1, long sC2, int zdiv,
    const float* Ag2, const float* Bg2, float* Cg2, const float* bias2, int shiftA2)
{
    if (gridDim.z > 1) {
        int z = blockIdx.z;
        Ag += (long)z * sA;
        Bg += (long)z * sB;
        Cg += (long)(z / zdiv) * sC1 + (long)(z % zdiv) * sC2;
    }
    if (blockIdx.y == 1) { Ag = Ag2; Bg = Bg2; Cg = Cg2; bias = bias2; shiftA = shiftA2; }

    extern __shared__ char smem[];
    const int tid = threadIdx.x;

    // raster: groups of 8 N-tiles, M-major inside group
    int bid = blockIdx.x;
    const int GW = 8;
    int tpg = MT * GW;
    int g = bid / tpg, r = bid % tpg;
    int n0 = g * GW;
    int gw = NT - n0; if (gw > GW) gw = GW;
    const int bm = (r / gw) * 256;        // 256-row M tile
    const int bn = (n0 + r % gw) * 128;   // 128-col N tile

#if TC_OK
    uint32_t SB   = (smem_addr_u32(smem) + 1023u) & ~1023u;
    uint32_t ctrl = SB + 2*STAGE_BYTES;   // [ctrl]=tmem ptr, [ctrl+16/+24]=mbar[0/1]

    if (tid < 32) {
        asm volatile("tcgen05.alloc.cta_group::1.sync.aligned.shared::cta.b32 [%0], %1;"
                     :: "r"(ctrl), "r"(256u) : "memory");
        asm volatile("tcgen05.relinquish_alloc_permit.cta_group::1.sync.aligned;");
    }
    if (tid == 0) { MBAR_INIT(ctrl+16, 1); MBAR_INIT(ctrl+24, 1); }
    __syncthreads();
    uint32_t tmem;
    asm("ld.shared.b32 %0, [%1];" : "=r"(tmem) : "r"(ctrl));

    const uint32_t idesc = (1u<<4) | (1u<<7) | (1u<<10) | (16u<<17) | (8u<<24); // bf16, f32 acc, N=128, M=128
    const int KT = K / GBK;

    // prologue: tile 0 -> stage 0
    ldsplit(Ag, K, bm,       0, SB,                 SB +   PLANE_BYTES, shiftA);
    ldsplit(Ag, K, bm + 128, 0, SB + 2*PLANE_BYTES, SB + 3*PLANE_BYTES, shiftA);
    ldsplit(Bg, K, bn,       0, SB + 4*PLANE_BYTES, SB + 5*PLANE_BYTES, 0);
    __syncthreads();

    int ph0 = 0, ph1 = 0;
    for (int kt = 0; kt < KT; ++kt) {
        const int s = kt & 1;
        if (tid == 0) {
            asm volatile("fence.proxy.async.shared::cta;" ::: "memory");
            uint32_t base = SB + s*STAGE_BYTES;
            uint64_t dBh = mk_desc(base + 4*PLANE_BYTES);
            uint64_t dBl = mk_desc(base + 5*PLANE_BYTES);
            uint32_t en0 = (kt > 0) ? 1u : 0u;
            #pragma unroll
            for (int half = 0; half < 2; ++half) {
                uint64_t dAh = mk_desc(base + half*2*PLANE_BYTES);
                uint64_t dAl = mk_desc(base + half*2*PLANE_BYTES + PLANE_BYTES);
                uint32_t dcol = tmem + half*128;
                uint32_t eh = en0;
                #pragma unroll
                for (int st = 0; st < 4; ++st) {
                    uint64_t o = 2*st;     // 16 bf16 = 32B = 2 x 16B units
                    mma_f16_ss(dcol, dAh + o, dBh + o, idesc, eh); eh = 1u;
                    mma_f16_ss(dcol, dAh + o, dBl + o, idesc, 1u);
                    mma_f16_ss(dcol, dAl + o, dBh + o, idesc, 1u);
                }
            }
            asm volatile("tcgen05.commit.cta_group::1.mbarrier::arrive::one.shared::cluster.b64 [%0];"
                         :: "r"(ctrl + 16 + 8*s) : "memory");
            if (kt >= 1 && kt + 1 < KT) {      // free the other stage
                int so = s ^ 1;
                if (so) { MBAR_WAIT(ctrl+24, ph1); ph1 ^= 1; }
                else    { MBAR_WAIT(ctrl+16, ph0); ph0 ^= 1; }
            }
        }
        __syncthreads();
        if (kt + 1 < KT) {
            uint32_t base = SB + (s^1)*STAGE_BYTES;
            int k0 = (kt+1)*GBK;
            ldsplit(Ag, K, bm,       k0, base,                 base +   PLANE_BYTES, shiftA);
            ldsplit(Ag, K, bm + 128, k0, base + 2*PLANE_BYTES, base + 3*PLANE_BYTES, shiftA);
            ldsplit(Bg, K, bn,       k0, base + 4*PLANE_BYTES, base + 5*PLANE_BYTES, 0);
        }
        __syncthreads();
    }
    if (tid == 0) {
        int sl = (KT-1) & 1;
        if (sl) { MBAR_WAIT(ctrl+24, ph1); }
        else    { MBAR_WAIT(ctrl+16, ph0); }
    }
    __syncthreads();
    asm volatile("tcgen05.fence::after_thread_sync;" ::: "memory");

    // epilogue: TMEM -> fp32 C ; warps 0-3: M-half 0, warps 4-7: M-half 1
    {
        const int wid = tid >> 5, lane = tid & 31;
        const int half = wid >> 2;
        const int row = bm + half*128 + (wid & 3)*32 + lane;
        #pragma unroll
        for (int cb = 0; cb < 128; cb += 32) {
            uint32_t rr[32];
            LDTM_X32(rr, tmem + half*128 + cb);
            asm volatile("tcgen05.wait::ld.sync.aligned;" ::: "memory");
            float* crow = Cg + (size_t)row*ldc + bn + cb;
            #pragma unroll
            for (int q4 = 0; q4 < 8; q4++) {
                float4 o4;
                float vv[4];
                #pragma unroll
                for (int t = 0; t < 4; t++) {
                    float v = alpha * __uint_as_float(rr[q4*4 + t]);
                    if (HASB) v += bias[bn + cb + q4*4 + t];
                    if (RELU) v = fmaxf(v, 0.f);
                    vv[t] = v;
                }
                o4.x = vv[0]; o4.y = vv[1]; o4.z = vv[2]; o4.w = vv[3];
                *(float4*)(crow + q4*4) = o4;
            }
        }
    }
    __syncthreads();
    if (tid < 32) {
        asm volatile("tcgen05.dealloc.cta_group::1.sync.aligned.b32 %0, %1;"
                     :: "r"(tmem), "r"(256u));
    }
#else
    // naive SIMT fallback — correctness-only body for the non-arch-specific
    // compilation pass; the sm_103a cubin above is what actually runs.
    (void)smem;
    for (int e = tid; e < 256*128; e += 256) {
        int i = e >> 7, j = e & 127;
        int gr = bm + i;
        bool zero = shiftA && ((gr & (TSEQ-1)) == 0);
        const float* arow = Ag + (size_t)(gr - shiftA)*K;
        const float* brow = Bg + (size_t)(bn + j)*K;
        float acc = 0.f;
        if (!zero)
            for (int k = 0; k < K; k++) acc += arow[k] * brow[k];
        float v = alpha * acc;
        if (HASB) v += bias[bn + j];
        if (RELU) v = fmaxf(v, 0.f);
        Cg[(size_t)gr*ldc + bn + j] = v;
    }
#endif
}

// ---------------- elementwise / glue kernels ----------------
__global__ void sub_b_kernel(const float* __restrict__ xin, const float* __restrict__ b)
{
    int i = blockIdx.x * 256 + threadIdx.x;
    g_x[i] = xin[i] - b[i % DIMIN];
}

__global__ void transpose_kernel(const float* __restrict__ D)  // -> g_Dt [DIMIN, WIDTH]
{
    __shared__ float t[32][33];
    int bx = blockIdx.x * 32;   // over DIMIN
    int by = blockIdx.y * 32;   // over WIDTH
    int x = threadIdx.x, y = threadIdx.y;  // 32 x 8
    #pragma unroll
    for (int i = 0; i < 32; i += 8)
        t[y+i][x] = D[(size_t)(by + y + i) * DIMIN + bx + x];
    __syncthreads();
    #pragma unroll
    for (int i = 0; i < 32; i += 8)
        g_Dt[(size_t)(bx + y + i) * WIDTH + by + x] = t[x][y+i];
}

__global__ void transpose_v_kernel()   // g_v [tok, W] -> g_vT per-batch [W, TSEQ]
{
    __shared__ float t[32][33];
    int bx = blockIdx.x * 32;   // over WIDTH
    int by = blockIdx.y * 32;   // over TSEQ
    int b  = blockIdx.z;
    int x = threadIdx.x, y = threadIdx.y;  // 32 x 8
    #pragma unroll
    for (int i = 0; i < 32; i += 8)
        t[y+i][x] = g_v[(size_t)(b*TSEQ + by + y + i) * WIDTH + bx + x];
    __syncthreads();
    #pragma unroll
    for (int i = 0; i < 32; i += 8)
        g_vT[(size_t)b*WIDTH*TSEQ + (size_t)(bx + y + i) * TSEQ + by + x] = t[x][y+i];
}

__global__ void attn_softmax_kernel()
{
    const int t  = blockIdx.x;
    const int bh = blockIdx.y;
    const int b  = bh >> 3, h = bh & 7;
    __shared__ float qs[DHQK];
    __shared__ float sc[TSEQ];
    __shared__ float red[128];
    const int tid = threadIdx.x;

    if (tid < DHQK) qs[tid] = g_q[(long)(b*TSEQ + t)*NEMBDS + h*DHQK + tid];
    __syncthreads();

    float lmax = -1e30f;
    for (int s = tid; s < TSEQ; s += 128) {
        float val = -1e30f;
        if (s <= t) {
            const float* kp = g_k + (long)(b*TSEQ + s)*NEMBDS + h*DHQK;
            float d = 0.f;
            #pragma unroll
            for (int i = 0; i < DHQK; i++) d += qs[i] * kp[i];
            val = d * 0.25f;
        }
        sc[s] = val;
        lmax = fmaxf(lmax, val);
    }
    red[tid] = lmax; __syncthreads();
    for (int o = 64; o > 0; o >>= 1) { if (tid < o) red[tid] = fmaxf(red[tid], red[tid+o]); __syncthreads(); }
    const float mx = red[0];
    __syncthreads();
    float lsum = 0.f;
    for (int s = tid; s < TSEQ; s += 128) {
        float e = (s <= t) ? expf(sc[s] - mx) : 0.f;
        sc[s] = e; lsum += e;
    }
    red[tid] = lsum; __syncthreads();
    for (int o = 64; o > 0; o >>= 1) { if (tid < o) red[tid] += red[tid+o]; __syncthreads(); }
    const float inv = 1.f / red[0];
    float* ap = g_att + ((long)bh * TSEQ + t) * TSEQ;
    for (int s = tid; s < TSEQ; s += 128) ap[s] = sc[s] * inv;
}

__global__ void proj_kernel()
{
    const int tok = blockIdx.x, tid = threadIdx.x;
    const float* dz = g_Dz + (long)tok * DIMIN;
    const float* xx = g_x  + (long)tok * DIMIN;
    float d1 = 0.f, d2 = 0.f;
    for (int i = tid; i < DIMIN; i += 256) { float a = dz[i]; d1 += a * xx[i]; d2 += a * a; }
    __shared__ float r1[256], r2[256];
    r1[tid] = d1; r2[tid] = d2; __syncthreads();
    for (int o = 128; o > 0; o >>= 1) { if (tid < o) { r1[tid] += r1[tid+o]; r2[tid] += r2[tid+o]; } __syncthreads(); }
    const float p = r1[0] / (r2[0] + 1e-6f);
    if (tid == 0) g_proj[tok] = p;
    for (int i = tid; i < DIMIN; i += 256)
        g_x2[(long)tok*DIMIN + i] = xx[i] - p * dz[i];
}

__global__ void topk_kernel()
{
    const int tok = blockIdx.x, tid = threadIdx.x;
    __shared__ float vals[WIDTH];
    __shared__ unsigned char sel[WIDTH];
    __shared__ float rv[256];
    __shared__ int   ri[256];
    const float* z = g_zin + (long)tok * WIDTH;
    for (int i = tid; i < WIDTH; i += 256) { vals[i] = z[i]; sel[i] = 0; }
    __syncthreads();
    for (int it = 0; it < KVAL; it++) {
        float bm2 = -1e30f; int bi = WIDTH;
        for (int i = tid; i < WIDTH; i += 256) {
            if (!sel[i]) {
                float x = vals[i];
                if (x > bm2) { bm2 = x; bi = i; }
            }
        }
        rv[tid] = bm2; ri[tid] = bi; __syncthreads();
        for (int o = 128; o > 0; o >>= 1) {
            if (tid < o) {
                float xv = rv[tid+o]; int xi = ri[tid+o];
                if (xv > rv[tid] || (xv == rv[tid] && xi < ri[tid])) { rv[tid] = xv; ri[tid] = xi; }
            }
            __syncthreads();
        }
        if (tid == 0) {
            g_tkv[tok*KVAL + it] = rv[0];
            g_tki[tok*KVAL + it] = ri[0];
            sel[ri[0]] = 1;
        }
        __syncthreads();
    }
}

__global__ void final_kernel(const float* __restrict__ D, const float* __restrict__ b,
                             float* __restrict__ out)
{
    const int tok = blockIdx.x, tid = threadIdx.x;
    __shared__ float v[KVAL];
    __shared__ int   id[KVAL];
    if (tid < KVAL) { v[tid] = g_tkv[tok*KVAL + tid]; id[tid] = g_tki[tok*KVAL + tid]; }
    __syncthreads();
    const float p = g_proj[tok];
    for (int n = tid; n < DIMIN; n += 256) {
        float a = p * g_Dz[(long)tok*DIMIN + n] + b[n];
        #pragma unroll 8
        for (int j = 0; j < KVAL; j++)
            a += v[j] * D[(long)id[j]*DIMIN + n];
        out[(long)tok*DIMIN + n] = a;
    }
}

// ---------------- host launch ----------------
extern "C" void kernel_launch(void* const* d_in, const int* in_sizes, int n_in,
                              void* d_out, int out_size)
{
    const float* x_input = (const float*)d_in[0];
    const float* D       = (const float*)d_in[1];
    const float* b       = (const float*)d_in[2];
    const float* Wk      = (const float*)d_in[3];
    const float* bk      = (const float*)d_in[4];
    const float* Wq      = (const float*)d_in[5];
    const float* bq      = (const float*)d_in[6];
    const float* Wv      = (const float*)d_in[7];
    const float* bv      = (const float*)d_in[8];
    const float* Wo      = (const float*)d_in[9];
    const float* bo      = (const float*)d_in[10];
    float* out = (float*)d_out;

    void *px, *px2, *pzin, *pq, *pk, *pv, *pvt, *patt, *po, *pzp, *pdz, *pdt;
    cudaGetSymbolAddress(&px,    g_x);
    cudaGetSymbolAddress(&px2,   g_x2);
    cudaGetSymbolAddress(&pzin,  g_zin);
    cudaGetSymbolAddress(&pq,    g_q);
    cudaGetSymbolAddress(&pk,    g_k);
    cudaGetSymbolAddress(&pv,    g_v);
    cudaGetSymbolAddress(&pvt,   g_vT);
    cudaGetSymbolAddress(&patt,  g_att);
    cudaGetSymbolAddress(&po,    g_o);
    cudaGetSymbolAddress(&pzp,   g_zp);
    cudaGetSymbolAddress(&pdz,   g_Dz);
    cudaGetSymbolAddress(&pdt,   g_Dt);

    cudaFuncSetAttribute(tgemm<false,false>, cudaFuncAttributeMaxDynamicSharedMemorySize, TG_DSMEM);
    cudaFuncSetAttribute(tgemm<false,true >, cudaFuncAttributeMaxDynamicSharedMemorySize, TG_DSMEM);
    cudaFuncSetAttribute(tgemm<true ,false>, cudaFuncAttributeMaxDynamicSharedMemorySize, TG_DSMEM);
    cudaFuncSetAttribute(tgemm<true ,true >, cudaFuncAttributeMaxDynamicSharedMemorySize, TG_DSMEM);

    // 1) x = x_input - b ; D^T
    sub_b_kernel<<<(NTOK*DIMIN)/256, 256>>>(x_input, b);
    transpose_kernel<<<dim3(DIMIN/32, WIDTH/32), dim3(32,8)>>>(D);

    // 2) z_in = relu(lam * x @ D^T)   M=4096(MT=16) N=8192(NT=64) K=768
    tgemm<true,false><<<dim3(16*64,1,1), 256, TG_DSMEM>>>(
        (const float*)px, D, (float*)pzin, nullptr,
        DIMIN, WIDTH, 16, 64, LAM, 0, 0,0,0,0,1,
        nullptr, nullptr, nullptr, nullptr, 0);

    // 3) q = z_in @ Wq^T + bq ; k = shift(z_in) @ Wk^T + bk  (grid.y pair)
    tgemm<false,true><<<dim3(16,2,1), 256, TG_DSMEM>>>(
        (const float*)pzin, Wq, (float*)pq, bq,
        WIDTH, NEMBDS, 16, 1, 1.0f, 0, 0,0,0,0,1,
        (const float*)pzin, Wk, (float*)pk, bk, 1);

    // 4) v = shift(z_in) @ Wv^T + bv   M=4096 N=8192 K=8192
    tgemm<false,true><<<dim3(16*64,1,1), 256, TG_DSMEM>>>(
        (const float*)pzin, Wv, (float*)pv, bv,
        WIDTH, WIDTH, 16, 64, 1.0f, 1, 0,0,0,0,1,
        nullptr, nullptr, nullptr, nullptr, 0);

    // 5) causal softmax
    attn_softmax_kernel<<<dim3(TSEQ, NBATCH*NHEADS), 128>>>();

    // 6) v^T per batch
    transpose_v_kernel<<<dim3(WIDTH/32, TSEQ/32, NBATCH), dim3(32,8)>>>();

    // 7) o = a @ vT^T batched over 64 (b,h): M=512(MT=2) N=1024(NT=8) K=512
    tgemm<false,false><<<dim3(2*8,1,NBATCH*NHEADS), 256, TG_DSMEM>>>(
        (const float*)patt, (const float*)pvt, (float*)po, nullptr,
        TSEQ, WIDTH, 2, 8, 1.0f, 0,
        (long)TSEQ*TSEQ, (long)DHV*TSEQ, (long)TSEQ*WIDTH, (long)DHV, NHEADS,
        nullptr, nullptr, nullptr, nullptr, 0);

    // 8) z_pred_ = relu(o @ Wo^T + bo)
    tgemm<true,true><<<dim3(16*64,1,1), 256, TG_DSMEM>>>(
        (const float*)po, Wo, (float*)pzp, bo,
        WIDTH, WIDTH, 16, 64, 1.0f, 0, 0,0,0,0,1,
        nullptr, nullptr, nullptr, nullptr, 0);

    // 9) Dz = z_pred_ @ D   N=768(NT=6) K=8192
    tgemm<false,false><<<dim3(16*6,1,1), 256, TG_DSMEM>>>(
        (const float*)pzp, (const float*)pdt, (float*)pdz, nullptr,
        WIDTH, DIMIN, 16, 6, 1.0f, 0, 0,0,0,0,1,
        nullptr, nullptr, nullptr, nullptr, 0);

    // 10) proj + x2
    proj_kernel<<<NTOK, 256>>>();

    // 11) z_novel = relu(lam * x2 @ D^T)
    tgemm<true,false><<<dim3(16*64,1,1), 256, TG_DSMEM>>>(
        (const float*)px2, D, (float*)pzin, nullptr,
        DIMIN, WIDTH, 16, 64, LAM, 0, 0,0,0,0,1,
        nullptr, nullptr, nullptr, nullptr, 0);

    // 12) top-32 per token
    topk_kernel<<<NTOK, 256>>>();

    // 13) out = proj*Dz + b + sparse(z_novel)@D
    final_kernel<<<NTOK, 256>>>(D, b, out);
}